// round 9
// baseline (speedup 1.0000x reference)
#include <cuda_runtime.h>
#include <cstdint>

#define KNB   32
#define KP    15
#define CIN   64
#define COUT  128
#define KTOT  (KP * CIN)     // 960
#define NMAX  65536
#define INV_SIGMA 10.0f

typedef unsigned long long u64;
typedef unsigned int u32;

__device__ float g_weighted[(size_t)NMAX * KTOT];   // 240MB scratch (tf32-rounded)
__device__ float g_Wt[COUT * KTOT];                 // W transposed [n][k], tf32-rounded

__device__ __forceinline__ void fma2(u64& d, u64 a, u64 b) {
    asm("fma.rn.f32x2 %0, %1, %2, %0;" : "+l"(d) : "l"(a), "l"(b));
}
__device__ __forceinline__ u32 tf32r(float x) {
    u32 r;
    asm("cvt.rna.tf32.f32 %0, %1;" : "=r"(r) : "f"(x));
    return r;
}

// ------------------------------------------------------------ W transpose (+tf32 round)
__global__ void wt_kernel(const float* __restrict__ W) {
    int i = blockIdx.x * 256 + threadIdx.x;     // over KTOT*COUT
    if (i < KTOT * COUT) {
        int k = i >> 7;          // KTOT index
        int n = i & 127;         // COUT index
        ((u32*)g_Wt)[n * KTOT + k] = tf32r(W[i]);
    }
}

// ---------------------------------------------------------------- stage 1+2
// 128 threads = 4 warps; each warp owns 2 points (16 lanes per point).
// Lane l: point p = l>>4, c-quad cg = l&15 (floats cg*4..cg*4+3).
// Each sInfl broadcast (half-warp) feeds 2 FFMA2 -> halves LDS pressure and
// doubles FFMA per LDS vs R7 layout.
#define PSTRIDE 484   // float2 stride per point region (padded: bank offset 8)

__global__ void __launch_bounds__(128)
stage12_kernel(const float* __restrict__ pos,
               const float* __restrict__ feats,
               const float* __restrict__ kpts,
               const void*  __restrict__ nbrs,
               int N)
{
    __shared__ float  sKP[KP * 3];
    __shared__ int    sNbr[4][2][KNB];
    __shared__ float2 sInfl[4 * 2 * PSTRIDE];   // dup pairs {v,v}, padded
    __shared__ int    sIs64;

    const int tid  = threadIdx.x;
    const int w    = tid >> 5;
    const int lane = tid & 31;
    const int base = blockIdx.x * 8;

    if (tid < KP * 3) sKP[tid] = kpts[tid];
    if (tid == 0) {
        // indices < 2^16: int64 little-endian => odd 32-bit words are 0
        const int* q = (const int*)nbrs;
        int zeros = 0;
#pragma unroll
        for (int i = 0; i < 32; i++) zeros += (q[2 * i + 1] == 0) ? 1 : 0;
        sIs64 = (zeros >= 30) ? 1 : 0;
    }
    __syncthreads();

    // ---- geometry: 2 passes cover 2 points x 32 neighbors
#pragma unroll
    for (int pass = 0; pass < 2; pass++) {
        const int p = pass;            // point within warp
        const int j = lane;            // neighbor
        const int n = base + w * 2 + p;
        if (n < N) {
            int nbi;
            if (sIs64) nbi = (int)((const long long*)nbrs)[(long long)n * KNB + j];
            else       nbi = ((const int*)nbrs)[n * KNB + j];
            sNbr[w][p][j] = nbi;
            const float rx = pos[3 * nbi + 0] - pos[3 * n + 0];
            const float ry = pos[3 * nbi + 1] - pos[3 * n + 1];
            const float rz = pos[3 * nbi + 2] - pos[3 * n + 2];
            float2* dst = sInfl + (w * 2 + p) * PSTRIDE + j;
#pragma unroll
            for (int kp = 0; kp < KP; kp++) {
                const float dx = rx - sKP[3 * kp + 0];
                const float dy = ry - sKP[3 * kp + 1];
                const float dz = rz - sKP[3 * kp + 2];
                const float dist = sqrtf(dx * dx + dy * dy + dz * dz);
                const float v = fmaxf(0.0f, 1.0f - dist * INV_SIGMA);
                dst[kp * KNB] = make_float2(v, v);
            }
        }
    }
    __syncwarp();

    // ---- aggregation
    const int p  = lane >> 4;
    const int cg = lane & 15;
    const int n  = base + w * 2 + p;
    if (n >= N) return;

    const float2* iBase = sInfl + (w * 2 + p) * PSTRIDE;
    const int*    nb    = sNbr[w][p];

    u64 acc[KP][2];
#pragma unroll
    for (int kp = 0; kp < KP; kp++) { acc[kp][0] = 0ULL; acc[kp][1] = 0ULL; }

#pragma unroll 2
    for (int j = 0; j < KNB; j++) {
        const float4 fv = *(const float4*)(feats + (size_t)nb[j] * CIN + cg * 4);
        u64 f01, f23;
        asm("mov.b64 %0, {%1, %2};" : "=l"(f01)
            : "r"(__float_as_uint(fv.x)), "r"(__float_as_uint(fv.y)));
        asm("mov.b64 %0, {%1, %2};" : "=l"(f23)
            : "r"(__float_as_uint(fv.z)), "r"(__float_as_uint(fv.w)));
#pragma unroll
        for (int kp = 0; kp < KP; kp++) {
            const u64 s = *(const u64*)(iBase + kp * KNB + j);   // half-warp bcast
            fma2(acc[kp][0], s, f01);
            fma2(acc[kp][1], s, f23);
        }
    }

    // store tf32-rounded c-quads (16B per kp per lane, coalesced)
    u32* gp = (u32*)(g_weighted + (size_t)n * KTOT + cg * 4);
#pragma unroll
    for (int kp = 0; kp < KP; kp++) {
        uint4 v;
        v.x = tf32r(__uint_as_float((u32)(acc[kp][0] & 0xFFFFFFFFULL)));
        v.y = tf32r(__uint_as_float((u32)(acc[kp][0] >> 32)));
        v.z = tf32r(__uint_as_float((u32)(acc[kp][1] & 0xFFFFFFFFULL)));
        v.w = tf32r(__uint_as_float((u32)(acc[kp][1] >> 32)));
        *(uint4*)(gp + kp * CIN) = v;
    }
}

// ------------------------------------------------------------------ stage 3
// out[N,128] = g_weighted[N,960] @ g_Wt^T  via mma.sync m16n8k8 tf32.
// CTA 128x128, K chunks of 32 (4 k8-steps), double-buffered smem.
// Smem per k8-step plane: [128 rows][8 k-interleaved], pos = 2*(k&3)+(k>>2),
// so fragment cols {c, c+4} are adjacent -> one lds.64 per fragment pair.
#define NC 30

__device__ __forceinline__ void mma_tf32(float* c, u32 a0, u32 a1, u32 a2, u32 a3,
                                         u32 b0, u32 b1) {
    asm("mma.sync.aligned.m16n8k8.row.col.f32.tf32.tf32.f32 "
        "{%0,%1,%2,%3}, {%4,%5,%6,%7}, {%8,%9}, {%0,%1,%2,%3};"
        : "+f"(c[0]), "+f"(c[1]), "+f"(c[2]), "+f"(c[3])
        : "r"(a0), "r"(a1), "r"(a2), "r"(a3), "r"(b0), "r"(b1));
}

__global__ void __launch_bounds__(256)
stage3_hmma(float* __restrict__ out, int N)
{
    extern __shared__ float sm[];   // As [2][4][128][8] @0 ; Bs same @8192
    const int tid  = threadIdx.x;
    const int w    = tid >> 5;
    const int lane = tid & 31;
    const int wm   = (w & 1) * 64;
    const int wn   = (w >> 1) * 32;
    const int m0   = blockIdx.x * 128;

    // global load mapping: thread -> row = tid>>1, 16 floats at hf
    const int row = tid >> 1;
    const int hf  = (tid & 1) * 16;
    const float* Ab = g_weighted + (size_t)(m0 + row) * KTOT + hf;
    const float* Bb = g_Wt + (size_t)row * KTOT + hf;

    float acc[4][4][4];
#pragma unroll
    for (int mt = 0; mt < 4; mt++)
#pragma unroll
        for (int nt = 0; nt < 4; nt++)
#pragma unroll
            for (int q = 0; q < 4; q++) acc[mt][nt][q] = 0.0f;

    float4 ar[4], br[4];

    // prefetch + stage chunk 0
#pragma unroll
    for (int i = 0; i < 4; i++) {
        ar[i] = *(const float4*)(Ab + i * 4);
        br[i] = *(const float4*)(Bb + i * 4);
    }
#pragma unroll
    for (int i = 0; i < 4; i++) {
        const int k0 = hf + i * 4;
        const int s  = k0 >> 3;
        const int bp = (k0 >> 2) & 1;
        float* Ad = sm + s * 1024 + row * 8 + bp;
        float* Bd = sm + 8192 + s * 1024 + row * 8 + bp;
        Ad[0] = ar[i].x; Ad[2] = ar[i].y; Ad[4] = ar[i].z; Ad[6] = ar[i].w;
        Bd[0] = br[i].x; Bd[2] = br[i].y; Bd[4] = br[i].z; Bd[6] = br[i].w;
    }
    __syncthreads();

    for (int c = 0; c < NC; c++) {
        const int cur = c & 1;
        if (c + 1 < NC) {
            const int ko = (c + 1) * 32;
#pragma unroll
            for (int i = 0; i < 4; i++) {
                ar[i] = *(const float4*)(Ab + ko + i * 4);
                br[i] = *(const float4*)(Bb + ko + i * 4);
            }
        }

        // compute on buffer cur: 4 k8-steps
#pragma unroll
        for (int s = 0; s < 4; s++) {
            const float* Abase = sm + cur * 4096 + s * 1024;
            const float* Bbase = sm + 8192 + cur * 4096 + s * 1024;
            u32 a[4][4];
#pragma unroll
            for (int mt = 0; mt < 4; mt++) {
                const int r0 = wm + mt * 16 + (lane >> 2);
                const uint2 lo = *(const uint2*)(Abase + r0 * 8 + 2 * (lane & 3));
                const uint2 hi = *(const uint2*)(Abase + (r0 + 8) * 8 + 2 * (lane & 3));
                a[mt][0] = lo.x; a[mt][1] = hi.x; a[mt][2] = lo.y; a[mt][3] = hi.y;
            }
#pragma unroll
            for (int nt = 0; nt < 4; nt++) {
                const int n = wn + nt * 8 + (lane >> 2);
                const uint2 bb = *(const uint2*)(Bbase + n * 8 + 2 * (lane & 3));
#pragma unroll
                for (int mt = 0; mt < 4; mt++)
                    mma_tf32(acc[mt][nt], a[mt][0], a[mt][1], a[mt][2], a[mt][3],
                             bb.x, bb.y);
            }
        }

        if (c + 1 < NC) {
            const int nxt = cur ^ 1;
#pragma unroll
            for (int i = 0; i < 4; i++) {
                const int k0 = hf + i * 4;
                const int s  = k0 >> 3;
                const int bp = (k0 >> 2) & 1;
                float* Ad = sm + nxt * 4096 + s * 1024 + row * 8 + bp;
                float* Bd = sm + 8192 + nxt * 4096 + s * 1024 + row * 8 + bp;
                Ad[0] = ar[i].x; Ad[2] = ar[i].y; Ad[4] = ar[i].z; Ad[6] = ar[i].w;
                Bd[0] = br[i].x; Bd[2] = br[i].y; Bd[4] = br[i].z; Bd[6] = br[i].w;
            }
            __syncthreads();
        }
    }

    // epilogue: c0,c1 -> (row, 2c+{0,1}); c2,c3 -> row+8
#pragma unroll
    for (int mt = 0; mt < 4; mt++) {
        const int r0 = m0 + wm + mt * 16 + (lane >> 2);
#pragma unroll
        for (int nt = 0; nt < 4; nt++) {
            const int n = wn + nt * 8 + 2 * (lane & 3);
            if (r0 < N)
                *(float2*)(out + (size_t)r0 * COUT + n) =
                    make_float2(acc[mt][nt][0], acc[mt][nt][1]);
            if (r0 + 8 < N)
                *(float2*)(out + (size_t)(r0 + 8) * COUT + n) =
                    make_float2(acc[mt][nt][2], acc[mt][nt][3]);
        }
    }
}

extern "C" void kernel_launch(void* const* d_in, const int* in_sizes, int n_in,
                              void* d_out, int out_size)
{
    const float* pos   = (const float*)d_in[0];
    const float* feats = (const float*)d_in[1];
    const float* kpts  = (const float*)d_in[2];
    const float* W     = (const float*)d_in[3];
    const void*  nbrs  = d_in[4];
    float* out = (float*)d_out;

    const int N = in_sizes[1] / CIN;   // feats is [N, CIN]

    const int SMEM = 2 * 4096 * 2 * 4;   // 64KB for stage3
    cudaFuncSetAttribute(stage3_hmma,
                         cudaFuncAttributeMaxDynamicSharedMemorySize, SMEM);

    wt_kernel<<<(KTOT * COUT + 255) / 256, 256>>>(W);

    stage12_kernel<<<(N + 7) / 8, 128>>>(pos, feats, kpts, nbrs, N);

    stage3_hmma<<<(N + 127) / 128, 256, SMEM>>>(out, N);
}